// round 3
// baseline (speedup 1.0000x reference)
#include <cuda_runtime.h>

#define TH 0.5f

// g_T1[m][j] = (sum_{i: bit i of m} W_hh[j][i]) + b_hh[j]   (index-order dot, bias folded)
__device__ float g_T1[256 * 8];
// g_SP[(n-1)*8 + j] = 128-bit spread pattern for first-spike-interval n (1..17),
//                     pre-shifted by channel j: bit (8t + j) of word t>>2 set iff (t+1)%n==0.
__device__ uint4 g_SP[17 * 8];
// g_tt[n] = exact fp32 breakpoint: minimal c with u_n(c) >= 0.5 under the
//           reference iteration u <- rn(rn(0.8*u) + c).  g_tt[0] = +huge sentinel.
__device__ float g_tt[18];

__device__ __forceinline__ float sim_u(float c, int n) {
    float u = 0.f;
    for (int k = 0; k < n; k++) u = __fadd_rn(__fmul_rn(0.8f, u), c);
    return u;
}

__global__ void build_tables(const float* __restrict__ W_hh,
                             const float* __restrict__ b_hh) {
    int tid = threadIdx.x;  // 256 threads

    // Folded layer-2 table
    {
        int m = tid;
#pragma unroll
        for (int j = 0; j < 8; j++) {
            float s = 0.f;
#pragma unroll
            for (int i = 0; i < 8; i++)
                if ((m >> i) & 1) s = __fadd_rn(s, W_hh[j * 8 + i]);
            g_T1[m * 8 + j] = __fadd_rn(s, b_hh[j]);
        }
    }

    // Exact first-spike breakpoints t_n: minimal fp32 c such that the n-step
    // no-reset trajectory reaches TH. u_n(c) is monotone nondecreasing in c,
    // so bitwise binary search is exact. Window is centered on the analytic
    // double value; walk-out loops are hard-capped (they need <=1 iteration in
    // practice; the cap only guards against a hang if assumptions break).
    if (tid < 16) {
        int n = tid + 1;
        double limd = 0.1 / (1.0 - pow(0.8, (double)n));
        unsigned ctr = __float_as_uint((float)limd);
        unsigned lo = ctr - 65536u, hi = ctr + 65536u;
        for (int it = 0; it < 64 && sim_u(__uint_as_float(lo), n) >= TH; it++)
            lo -= 1u << 20;
        for (int it = 0; it < 64 && sim_u(__uint_as_float(hi), n) <  TH; it++)
            hi += 1u << 20;
        while (hi - lo > 1u) {            // <= 32 iterations by construction
            unsigned mid = lo + ((hi - lo) >> 1);
            if (sim_u(__uint_as_float(mid), n) >= TH) hi = mid; else lo = mid;
        }
        g_tt[n] = __uint_as_float(hi);
    }
    if (tid == 16) { g_tt[0] = 3.0e38f; g_tt[17] = -3.0e38f; }

    // Pre-shifted spread patterns
    if (tid < 17 * 8) {
        int row = tid >> 3;      // n-1
        int j = tid & 7;
        int n = row + 1;         // 1..17 (17 = never spikes -> zeros)
        unsigned w[4] = {0u, 0u, 0u, 0u};
        if (n <= 16)
            for (int t = 0; t < 16; t++)
                if ((t + 1) % n == 0) w[t >> 2] |= 1u << (8 * (t & 3) + j);
        g_SP[tid] = make_uint4(w[0], w[1], w[2], w[3]);
    }
}

__global__ __launch_bounds__(256) void snn_kernel(
    const float* __restrict__ x,
    const float* __restrict__ W_ih,
    const float* __restrict__ b_ih,
    const float* __restrict__ W_ho,
    const float* __restrict__ b_ho,
    float* __restrict__ out,
    int B)
{
    __shared__ float4 sT1[512];     // folded layer-2 table, float4 pairs
    __shared__ uint4  sSP[17 * 8];  // spread patterns
    __shared__ float  stt[18];      // breakpoints

    int tid = threadIdx.x;
    const float4* gt1 = reinterpret_cast<const float4*>(g_T1);
    sT1[tid]       = gt1[tid];
    sT1[tid + 256] = gt1[tid + 256];
    if (tid < 136) sSP[tid] = g_SP[tid];
    if (tid < 18)  stt[tid] = g_tt[tid];
    __syncthreads();

    int idx = blockIdx.x * 256 + tid;
    if (idx >= B) return;

    float2 xv = reinterpret_cast<const float2*>(x)[idx];

    float who[8];
#pragma unroll
    for (int j = 0; j < 8; j++) who[j] = W_ho[j];
    float bo = b_ho[0];

    // ---- Layer 1: compute first-spike interval per channel, assemble all 16
    //      per-step spike masks as 16 packed bytes (bit-exact vs iteration). ----
    unsigned Mw0 = 0, Mw1 = 0, Mw2 = 0, Mw3 = 0;
#pragma unroll
    for (int j = 0; j < 8; j++) {
        float c = __fadd_rn(
            __fadd_rn(__fmul_rn(xv.x, W_ih[2 * j]),
                      __fmul_rn(xv.y, W_ih[2 * j + 1])),
            b_ih[j]);
        // Approximate n* = log_{0.8}(1 - 0.1/c), then exact +-1 correction.
        // c <= 0.1 gives r <= 0 -> log2f NaN -> cvt 0 -> clamp 1; the final
        // stt[16] guard then forces n=17 (never spikes), which is correct
        // because such c cannot reach TH within 16 steps.
        float r = 1.0f - __fdividef(0.1f, c);
        int n = __float2int_ru(__log2f(r) * -3.10628372f);
        n = min(max(n, 1), 16);
        n -= (c >= stt[n - 1]) ? 1 : 0;   // stt[0] = +huge, never fires at n=0
        n += (c <  stt[n])     ? 1 : 0;   // may push to 17
        n = (c >= stt[16]) ? n : 17;      // below smallest breakpoint: never spikes
        uint4 p = sSP[(n - 1) * 8 + j];
        Mw0 |= p.x; Mw1 |= p.y; Mw2 |= p.z; Mw3 |= p.w;
    }
    unsigned Mw[4] = {Mw0, Mw1, Mw2, Mw3};

    // ---- Layers 2 + 3: 16-step simulation, layer-1 mask = 1 byte extract ----
    float m2[8];
#pragma unroll
    for (int j = 0; j < 8; j++) m2[j] = 0.f;
    float mo = 0.f, cnt = 0.f;

#pragma unroll
    for (int t = 0; t < 16; t++) {
        unsigned mk = __byte_perm(Mw[t >> 2], 0u, 0x4440 | (t & 3));
        float4 A  = sT1[2 * mk];
        float4 Bv = sT1[2 * mk + 1];
        float tt8[8] = {A.x, A.y, A.z, A.w, Bv.x, Bv.y, Bv.z, Bv.w};

        float acc = 0.f;
#pragma unroll
        for (int j = 0; j < 8; j++) {
            float v = fmaf(0.8f, m2[j], tt8[j]);   // table already holds dot + b_hh
            bool s = (v >= TH);
            if (s) acc += who[j];                  // predicated FADD, reuses predicate
            m2[j] = s ? 0.f : v;
        }

        float vo = __fadd_rn(fmaf(0.8f, mo, acc), bo);
        bool so = (vo >= TH);
        cnt += so ? 1.f : 0.f;
        mo = so ? 0.f : vo;
    }

    out[idx] = cnt * 0.0625f;
}

extern "C" void kernel_launch(void* const* d_in, const int* in_sizes, int n_in,
                              void* d_out, int out_size) {
    const float* x    = (const float*)d_in[0];
    const float* W_ih = (const float*)d_in[1];
    const float* b_ih = (const float*)d_in[2];
    const float* W_hh = (const float*)d_in[3];
    const float* b_hh = (const float*)d_in[4];
    const float* W_ho = (const float*)d_in[5];
    const float* b_ho = (const float*)d_in[6];

    int B = in_sizes[0] / 2;

    build_tables<<<1, 256>>>(W_hh, b_hh);
    snn_kernel<<<(B + 255) / 256, 256>>>(x, W_ih, b_ih, W_ho, b_ho,
                                         (float*)d_out, B);
}

// round 4
// speedup vs baseline: 1.1521x; 1.1521x over previous
#include <cuda_runtime.h>

#define TH 0.5f

// g_T1[m][j] = (sum_{i: bit i of m} W_hh[j][i]) + b_hh[j]   (index-order dot, bias folded)
__device__ float g_T1[256 * 8];
// g_SP[(n-1)*8 + j] = 128-bit spread pattern for first-spike-interval n (1..17),
//                     pre-shifted by channel j: bit (8t + j) of word t>>2 set iff (t+1)%n==0.
__device__ uint4 g_SP[17 * 8];
// g_tt[n] = exact fp32 breakpoint: minimal c with u_n(c) >= 0.5 under the
//           reference iteration u <- rn(rn(0.8*u) + c).  g_tt[0] = +huge sentinel.
__device__ float g_tt[18];

__device__ __forceinline__ float sim_u(float c, int n) {
    float u = 0.f;
    for (int k = 0; k < n; k++) u = __fadd_rn(__fmul_rn(0.8f, u), c);
    return u;
}

__global__ void build_tables(const float* __restrict__ W_hh,
                             const float* __restrict__ b_hh) {
    int tid = threadIdx.x;  // 256 threads = 8 warps

    // ---- Folded layer-2 table ----
    {
        int m = tid;
#pragma unroll
        for (int j = 0; j < 8; j++) {
            float s = 0.f;
#pragma unroll
            for (int i = 0; i < 8; i++)
                if ((m >> i) & 1) s = __fadd_rn(s, W_hh[j * 8 + i]);
            g_T1[m * 8 + j] = __fadd_rn(s, b_hh[j]);
        }
    }

    // ---- Exact first-spike breakpoints: warp-parallel 32-ary search. ----
    // u_n(c) is monotone nondecreasing in c, so the minimal fp32 c with
    // u_n(c) >= TH is well-defined; 4 ballot rounds narrow a +-2^19-ULP window
    // (analytic center is within ~32 ULPs), then a capped exact walk verifies.
    {
        int wid = tid >> 5, lane = tid & 31;
        for (int rep = 0; rep < 2; rep++) {
            int n = wid + 8 * rep + 1;  // 1..16
            double p = 1.0;
            for (int k = 0; k < n; k++) p *= 0.8;
            double limd = 0.1 / (1.0 - p);
            unsigned lo = __float_as_uint((float)limd) - (1u << 19);
            // Invariant: answer in (lo, lo + 2^20]; each round divides by 32.
#pragma unroll
            for (int round = 0; round < 4; round++) {
                unsigned step = 1u << (15 - 5 * round);
                unsigned cand = lo + (lane + 1u) * step;
                unsigned bal = __ballot_sync(0xFFFFFFFFu,
                                             sim_u(__uint_as_float(cand), n) >= TH);
                unsigned k = bal ? (__ffs(bal) - 1u) : 31u;
                lo = lo + k * step;  // f(lo) false (or window edge)
            }
            unsigned ans = lo + 1u;  // minimal true candidate from last round
            // Capped exact verification walk (no-ops in practice).
            for (int g = 0; g < 8 && sim_u(__uint_as_float(ans - 1u), n) >= TH; g++) ans--;
            for (int g = 0; g < 8 && sim_u(__uint_as_float(ans), n) < TH; g++) ans++;
            if (lane == 0) g_tt[n] = __uint_as_float(ans);
        }
    }
    if (tid == 0) { g_tt[0] = 3.0e38f; g_tt[17] = -3.0e38f; }

    // ---- Pre-shifted spread patterns ----
    if (tid < 17 * 8) {
        int row = tid >> 3;      // n-1
        int j = tid & 7;
        int n = row + 1;         // 1..17 (17 = never spikes -> zeros)
        unsigned w[4] = {0u, 0u, 0u, 0u};
        if (n <= 16)
            for (int t = 0; t < 16; t++)
                if ((t + 1) % n == 0) w[t >> 2] |= 1u << (8 * (t & 3) + j);
        g_SP[tid] = make_uint4(w[0], w[1], w[2], w[3]);
    }
}

__global__ __launch_bounds__(256) void snn_kernel(
    const float* __restrict__ x,
    const float* __restrict__ W_ih,
    const float* __restrict__ b_ih,
    const float* __restrict__ W_ho,
    const float* __restrict__ b_ho,
    float* __restrict__ out,
    int B)
{
    // Table split into two 16B-stride arrays: addr = mk*16 -> bank-quad = mk mod 8
    // reaches all 8 quads (the old 32B stride aliased to even quads only,
    // guaranteeing >=2-way conflicts every phase).
    __shared__ float4 sA[256];      // g_T1 entry m, floats 0..3
    __shared__ float4 sB[256];      // g_T1 entry m, floats 4..7
    __shared__ uint4  sSP[17 * 8];  // spread patterns
    __shared__ float  stt[18];      // breakpoints

    int tid = threadIdx.x;
    const float4* gt1 = reinterpret_cast<const float4*>(g_T1);
    sA[tid] = gt1[2 * tid];
    sB[tid] = gt1[2 * tid + 1];
    if (tid < 136) sSP[tid] = g_SP[tid];
    if (tid < 18)  stt[tid] = g_tt[tid];
    __syncthreads();

    int idx = blockIdx.x * 256 + tid;
    if (idx >= B) return;

    float2 xv = reinterpret_cast<const float2*>(x)[idx];

    float who[8];
#pragma unroll
    for (int j = 0; j < 8; j++) who[j] = W_ho[j];
    float bo = b_ho[0];

    // ---- Layer 1: compute first-spike interval per channel, assemble all 16
    //      per-step spike masks as 16 packed bytes (bit-exact vs iteration). ----
    unsigned Mw0 = 0, Mw1 = 0, Mw2 = 0, Mw3 = 0;
#pragma unroll
    for (int j = 0; j < 8; j++) {
        float c = __fadd_rn(
            __fadd_rn(__fmul_rn(xv.x, W_ih[2 * j]),
                      __fmul_rn(xv.y, W_ih[2 * j + 1])),
            b_ih[j]);
        // Approximate n* = log_{0.8}(1 - 0.1/c), then exact +-1 correction.
        // c <= 0.1 -> r <= 0 -> log2f NaN -> cvt 0 -> clamp; stt[16] guard
        // forces n=17 (never spikes), correct since such c can't reach TH.
        float r = 1.0f - __fdividef(0.1f, c);
        int n = __float2int_ru(__log2f(r) * -3.10628372f);
        n = min(max(n, 1), 16);
        n -= (c >= stt[n - 1]) ? 1 : 0;   // stt[0] = +huge
        n += (c <  stt[n])     ? 1 : 0;   // may push to 17
        n = (c >= stt[16]) ? n : 17;      // never spikes within 16 steps
        uint4 p = sSP[(n - 1) * 8 + j];
        Mw0 |= p.x; Mw1 |= p.y; Mw2 |= p.z; Mw3 |= p.w;
    }
    unsigned Mw[4] = {Mw0, Mw1, Mw2, Mw3};

    // ---- Layers 2 + 3: 16-step simulation, layer-1 mask = 1 byte extract ----
    float m2[8];
#pragma unroll
    for (int j = 0; j < 8; j++) m2[j] = 0.f;
    float mo = 0.f, cnt = 0.f;

#pragma unroll
    for (int t = 0; t < 16; t++) {
        unsigned mk = __byte_perm(Mw[t >> 2], 0u, 0x4440 | (t & 3));
        float4 A  = sA[mk];
        float4 Bv = sB[mk];
        float tt8[8] = {A.x, A.y, A.z, A.w, Bv.x, Bv.y, Bv.z, Bv.w};

        float acc = 0.f;
#pragma unroll
        for (int j = 0; j < 8; j++) {
            float v = fmaf(0.8f, m2[j], tt8[j]);   // table already holds dot + b_hh
            bool s = (v >= TH);
            if (s) acc += who[j];                  // predicated FADD
            m2[j] = s ? 0.f : v;
        }

        float vo = __fadd_rn(fmaf(0.8f, mo, acc), bo);
        bool so = (vo >= TH);
        cnt += so ? 1.f : 0.f;
        mo = so ? 0.f : vo;
    }

    out[idx] = cnt * 0.0625f;
}

extern "C" void kernel_launch(void* const* d_in, const int* in_sizes, int n_in,
                              void* d_out, int out_size) {
    const float* x    = (const float*)d_in[0];
    const float* W_ih = (const float*)d_in[1];
    const float* b_ih = (const float*)d_in[2];
    const float* W_hh = (const float*)d_in[3];
    const float* b_hh = (const float*)d_in[4];
    const float* W_ho = (const float*)d_in[5];
    const float* b_ho = (const float*)d_in[6];

    int B = in_sizes[0] / 2;

    build_tables<<<1, 256>>>(W_hh, b_hh);
    snn_kernel<<<(B + 255) / 256, 256>>>(x, W_ih, b_ih, W_ho, b_ho,
                                         (float*)d_out, B);
}

// round 5
// speedup vs baseline: 1.7384x; 1.5089x over previous
#include <cuda_runtime.h>
#include <cstring>

#define TH 0.5f

struct Params {
    uint4 SPb[17];  // base spike patterns: bit 8*(t&3) of word t>>2 set iff (t+1)%n==0, n=idx+1 (idx 16 -> zeros)
    float tt[16];   // tt[k] = minimal fp32 c with u_{k+1}(c) >= TH under u <- rn(rn(0.8*u)+c)  (strictly decreasing)
};

// Dynamic smem layout (all table reads conflict-free: quad = lane&7)
static const int SM_A   = 0;                  // table half A, 8 copies: entry m, copy r at m*128 + r*16
static const int SM_B   = 32768;              // table half B
static const int SM_SP  = 65536;              // base patterns, 8 copies: (n-1)*128 + r*16
static const int SM_WIH = SM_SP + 17 * 128;   // W_ih 16 floats
static const int SM_BIH = SM_WIH + 64;        // b_ih 8 floats
static const int SM_WHH = SM_BIH + 32;        // W_hh 64 floats (prologue only)
static const int SM_BHH = SM_WHH + 256;       // b_hh 8 floats (prologue only)
static const int SMEM_BYTES = SM_BHH + 32;    // 68096

__global__ __launch_bounds__(256, 3) void snn_kernel(
    const float2* __restrict__ x,
    const float* __restrict__ W_ih,
    const float* __restrict__ b_ih,
    const float* __restrict__ W_hh,
    const float* __restrict__ b_hh,
    const float* __restrict__ W_ho,
    const float* __restrict__ b_ho,
    float* __restrict__ out,
    int B, Params P)
{
    extern __shared__ __align__(128) char sm[];
    int tid = threadIdx.x;

    // ---- stage raw weights ----
    if (tid < 64)       ((float*)(sm + SM_WHH))[tid]      = W_hh[tid];
    else if (tid < 72)  ((float*)(sm + SM_BHH))[tid - 64] = b_hh[tid - 64];
    else if (tid < 88)  ((float*)(sm + SM_WIH))[tid - 72] = W_ih[tid - 72];
    else if (tid < 96)  ((float*)(sm + SM_BIH))[tid - 88] = b_ih[tid - 88];
    __syncthreads();

    // ---- per-block table build: thread tid owns entry m = tid.
    //      Adding +0.0f for unset bits is a bitwise identity (s is never -0),
    //      so partial sums match set-bit-only sequential accumulation exactly. ----
    float ent[8];
    {
        const float* whh = (const float*)(sm + SM_WHH);
        const float* bhh = (const float*)(sm + SM_BHH);
#pragma unroll
        for (int j = 0; j < 8; j++) {
            float s = 0.f;
#pragma unroll
            for (int i = 0; i < 8; i++)
                s = __fadd_rn(s, ((tid >> i) & 1) ? whh[j * 8 + i] : 0.f);
            ent[j] = __fadd_rn(s, bhh[j]);   // fold b_hh into table
        }
    }
    {
        float4 ea = make_float4(ent[0], ent[1], ent[2], ent[3]);
        float4 eb = make_float4(ent[4], ent[5], ent[6], ent[7]);
#pragma unroll
        for (int p = 0; p < 8; p++) {
            int r = (tid + p) & 7;           // rotation keeps stores conflict-free
            *(float4*)(sm + SM_A + tid * 128 + r * 16) = ea;
            *(float4*)(sm + SM_B + tid * 128 + r * 16) = eb;
        }
    }
    if (tid < 136) {
        int r = tid / 17, n1 = tid % 17;
        *(uint4*)(sm + SM_SP + n1 * 128 + r * 16) = P.SPb[n1];
    }
    __syncthreads();

    const char* tabA = sm + SM_A  + (tid & 7) * 16;
    const char* tabB = sm + SM_B  + (tid & 7) * 16;
    const char* tabS = sm + SM_SP + (tid & 7) * 16;
    const float* swih = (const float*)(sm + SM_WIH);
    const float* sbih = (const float*)(sm + SM_BIH);

    float tt[16];
#pragma unroll
    for (int k = 0; k < 16; k++) tt[k] = P.tt[k];
    float who[8];
#pragma unroll
    for (int j = 0; j < 8; j++) who[j] = W_ho[j];
    float bo = b_ho[0];

    int TOT = gridDim.x * 256;
    for (int e = blockIdx.x * 256 + tid; e < B; e += TOT) {
        float2 xv = x[e];

        // ---- Layer 1: exact first-spike interval via 16 breakpoint compares
        //      (no MUFU), then OR of channel-shifted base patterns. ----
        unsigned M0 = 0, M1 = 0, M2 = 0, M3 = 0;
#pragma unroll
        for (int j = 0; j < 8; j++) {
            float c = __fadd_rn(
                __fadd_rn(__fmul_rn(xv.x, swih[2 * j]),
                          __fmul_rn(xv.y, swih[2 * j + 1])),
                sbih[j]);
            int n1 = 0;   // n-1; c<=0 or tiny c -> all compares true -> 16 (never spikes)
#pragma unroll
            for (int k = 0; k < 16; k++) n1 += (c < tt[k]) ? 1 : 0;
            uint4 pb = *(const uint4*)(tabS + n1 * 128);
            // pattern bits live at positions 8t: <<j stays within each byte
            M0 |= pb.x << j; M1 |= pb.y << j; M2 |= pb.z << j; M3 |= pb.w << j;
        }
        unsigned Mw[4] = {M0, M1, M2, M3};

        // ---- Layers 2 + 3 ----
        float m2[8];
#pragma unroll
        for (int j = 0; j < 8; j++) m2[j] = 0.f;
        float mo = 0.f, cnt = 0.f;

#pragma unroll
        for (int t = 0; t < 16; t++) {
            unsigned mk = __byte_perm(Mw[t >> 2], 0u, 0x4440 | (t & 3));
            float4 A  = *(const float4*)(tabA + mk * 128);
            float4 Bv = *(const float4*)(tabB + mk * 128);
            float tt8[8] = {A.x, A.y, A.z, A.w, Bv.x, Bv.y, Bv.z, Bv.w};

            float acc = 0.f;
#pragma unroll
            for (int j = 0; j < 8; j++) {
                float v = fmaf(0.8f, m2[j], tt8[j]);  // table holds dot + b_hh
                bool s = (v >= TH);
                if (s) acc += who[j];                 // serial j-order (matches passing kernels)
                m2[j] = s ? 0.f : v;
            }

            float vo = __fadd_rn(fmaf(0.8f, mo, acc), bo);
            bool so = (vo >= TH);
            cnt += so ? 1.f : 0.f;
            mo = so ? 0.f : vo;
        }

        out[e] = cnt * 0.0625f;
    }
}

// Host-side replica of the device fp32 iteration. volatile forces each op to
// round to fp32 and forbids FMA contraction -> bit-identical to __fmul_rn/__fadd_rn.
static float host_sim(float c, int n) {
    volatile float u = 0.f;
    for (int k = 0; k < n; k++) { volatile float t = 0.8f * u; u = t + c; }
    return u;
}

extern "C" void kernel_launch(void* const* d_in, const int* in_sizes, int n_in,
                              void* d_out, int out_size) {
    const float2* x   = (const float2*)d_in[0];
    const float* W_ih = (const float*)d_in[1];
    const float* b_ih = (const float*)d_in[2];
    const float* W_hh = (const float*)d_in[3];
    const float* b_hh = (const float*)d_in[4];
    const float* W_ho = (const float*)d_in[5];
    const float* b_ho = (const float*)d_in[6];

    int B = in_sizes[0] / 2;

    Params P;
    // Exact breakpoints: bitwise bisection over positive floats (monotone in bits).
    // f(0.05) is false for all n (limit 0.25 < TH); f(4.0) is true for all n.
    for (int n = 1; n <= 16; n++) {
        float flo = 0.05f, fhi = 4.0f;
        unsigned lo, hi;
        memcpy(&lo, &flo, 4); memcpy(&hi, &fhi, 4);
        while (hi - lo > 1u) {
            unsigned mid = lo + (hi - lo) / 2;
            float fm; memcpy(&fm, &mid, 4);
            if (host_sim(fm, n) >= TH) hi = mid; else lo = mid;
        }
        memcpy(&P.tt[n - 1], &hi, 4);
    }
    // Base spike patterns (period-n trains over 16 steps), idx 16 = never.
    for (int n1 = 0; n1 < 17; n1++) {
        unsigned w[4] = {0u, 0u, 0u, 0u};
        int n = n1 + 1;
        if (n <= 16)
            for (int t = 0; t < 16; t++)
                if ((t + 1) % n == 0) w[t >> 2] |= 1u << (8 * (t & 3));
        P.SPb[n1].x = w[0]; P.SPb[n1].y = w[1];
        P.SPb[n1].z = w[2]; P.SPb[n1].w = w[3];
    }

    cudaFuncSetAttribute(snn_kernel,
                         cudaFuncAttributeMaxDynamicSharedMemorySize, SMEM_BYTES);

    snn_kernel<<<444, 256, SMEM_BYTES>>>(x, W_ih, b_ih, W_hh, b_hh, W_ho, b_ho,
                                         (float*)d_out, B, P);
}

// round 6
// speedup vs baseline: 2.0390x; 1.1730x over previous
#include <cuda_runtime.h>
#include <cstring>

#define TH 0.5f

using ull = unsigned long long;

struct Params {
    uint4 SPb[17];  // base spike patterns (j=0): bit 8*(t&3) of word t>>2 set iff (t+1)%n==0
    float tt[16];   // exact breakpoints, strictly decreasing: tt[k] = min fp32 c with u_{k+1}(c) >= TH
};

// ---- dynamic smem layout (all hot reads conflict-free via r = lane&7 copy) ----
static const int SM_A   = 0;                   // table half A: entry m at m*128 + r*16   (32768)
static const int SM_B   = 32768;               // table half B                            (32768)
static const int SM_SP  = 65536;               // pre-shifted patterns: (n1*8+j)*128+r*16 (17408)
static const int SM_TTG = SM_SP + 17408;       // tt groups of 4: g*128 + r*16            (512)
static const int SM_WP  = SM_TTG + 512;        // packed W_ih/b_ih channel-pair splats    (128)
static const int SMEM_BYTES = SM_WP + 128;     // 83584

// ---- packed f32x2 helpers: per-lane fp32 rn, bitwise == scalar ops ----
__device__ __forceinline__ ull pk(float lo, float hi) {
    ull r; asm("mov.b64 %0, {%1, %2};" : "=l"(r) : "f"(lo), "f"(hi)); return r;
}
__device__ __forceinline__ void upk(float& lo, float& hi, ull v) {
    asm("mov.b64 {%0, %1}, %2;" : "=f"(lo), "=f"(hi) : "l"(v));
}
__device__ __forceinline__ ull mul2(ull a, ull b) {
    ull d; asm("mul.rn.f32x2 %0, %1, %2;" : "=l"(d) : "l"(a), "l"(b)); return d;
}
__device__ __forceinline__ ull add2(ull a, ull b) {
    ull d; asm("add.rn.f32x2 %0, %1, %2;" : "=l"(d) : "l"(a), "l"(b)); return d;
}
__device__ __forceinline__ ull fma2(ull a, ull b, ull c) {
    ull d; asm("fma.rn.f32x2 %0, %1, %2, %3;" : "=l"(d) : "l"(a), "l"(b), "l"(c)); return d;
}

__global__ __launch_bounds__(256, 2) void snn_kernel(
    const float4* __restrict__ x2,      // adjacent element pairs
    const float* __restrict__ W_ih,
    const float* __restrict__ b_ih,
    const float* __restrict__ W_hh,
    const float* __restrict__ b_hh,
    const float* __restrict__ W_ho,
    const float* __restrict__ b_ho,
    float2* __restrict__ out,
    int NP, Params P)
{
    extern __shared__ __align__(128) char sm[];
    int tid = threadIdx.x;

    // ---- prologue: per-block table build (values bitwise == round-5 build) ----
    {
        float ent[8];
#pragma unroll
        for (int j = 0; j < 8; j++) {
            float s = 0.f;
#pragma unroll
            for (int i = 0; i < 8; i++)
                s = __fadd_rn(s, ((tid >> i) & 1) ? W_hh[j * 8 + i] : 0.f);
            ent[j] = __fadd_rn(s, b_hh[j]);
        }
        float4 ea = make_float4(ent[0], ent[1], ent[2], ent[3]);
        float4 eb = make_float4(ent[4], ent[5], ent[6], ent[7]);
#pragma unroll
        for (int p = 0; p < 8; p++) {
            int r = (tid + p) & 7;
            *(float4*)(sm + SM_A + tid * 128 + r * 16) = ea;
            *(float4*)(sm + SM_B + tid * 128 + r * 16) = eb;
        }
    }
    for (int i = tid; i < 136 * 8; i += 256) {   // pre-shifted patterns, 8 copies
        int e = i >> 3, r = i & 7;
        int n1 = e >> 3, j = e & 7;
        uint4 b = P.SPb[n1];
        *(uint4*)(sm + SM_SP + e * 128 + r * 16) =
            make_uint4(b.x << j, b.y << j, b.z << j, b.w << j);
    }
    if (tid < 32) {                              // tt groups of 4, 8 copies
        int g = tid >> 3, r = tid & 7;
        *(float4*)(sm + SM_TTG + g * 128 + r * 16) =
            make_float4(P.tt[4 * g], P.tt[4 * g + 1], P.tt[4 * g + 2], P.tt[4 * g + 3]);
    }
    if (tid < 4) {                               // channel-pair splats of W_ih / b_ih
        int p2 = tid;
        ((float2*)(sm + SM_WP))[p2]      = make_float2(W_ih[4 * p2],     W_ih[4 * p2 + 2]);
        ((float2*)(sm + SM_WP + 32))[p2] = make_float2(W_ih[4 * p2 + 1], W_ih[4 * p2 + 3]);
        ((float2*)(sm + SM_WP + 64))[p2] = make_float2(b_ih[2 * p2],     b_ih[2 * p2 + 1]);
    }
    __syncthreads();

    const char* tA   = sm + SM_A   + (tid & 7) * 16;
    const char* tB   = sm + SM_B   + (tid & 7) * 16;
    const char* tSP  = sm + SM_SP  + (tid & 7) * 16;
    const char* tTTG = sm + SM_TTG + (tid & 7) * 16;

    float who[8];
#pragma unroll
    for (int j = 0; j < 8; j++) who[j] = W_ho[j];
    float bo = b_ho[0];

    const ull L2 = 0x3F4CCCCD3F4CCCCDULL;  // {0.8f, 0.8f}

    int TOT = gridDim.x * 256;
    for (int g = blockIdx.x * 256 + tid; g < NP; g += TOT) {
        float4 xx = x2[g];   // elem0 = (x,y), elem1 = (z,w)

        // ---- Layer 1 for both elements: packed c, two-level exact count ----
        unsigned Mw[2][4] = {{0,0,0,0},{0,0,0,0}};
#pragma unroll
        for (int el = 0; el < 2; el++) {
            float X0 = el ? xx.z : xx.x;
            float X1 = el ? xx.w : xx.y;
            ull x0s = pk(X0, X0), x1s = pk(X1, X1);
#pragma unroll
            for (int p2 = 0; p2 < 4; p2++) {
                ull w0p = *(const ull*)(sm + SM_WP +      p2 * 8);
                ull w1p = *(const ull*)(sm + SM_WP + 32 + p2 * 8);
                ull bp  = *(const ull*)(sm + SM_WP + 64 + p2 * 8);
                // per-lane: rn(rn(rn(x0*w0) + rn(x1*w1)) + b) — same as round 5
                ull c2 = add2(add2(mul2(x0s, w0p), mul2(x1s, w1p)), bp);
                float cf[2]; upk(cf[0], cf[1], c2);
#pragma unroll
                for (int h = 0; h < 2; h++) {
                    float c = cf[h];
                    int j = 2 * p2 + h;
                    // coarse: pick group of 4 (pivot compares use constant-bank operands)
                    int nb = ((c < P.tt[3])  ? 4 : 0)
                           + ((c < P.tt[7])  ? 4 : 0)
                           + ((c < P.tt[11]) ? 4 : 0);
                    float4 gq = *(const float4*)(tTTG + nb * 32);
                    int n1 = nb + ((c < gq.x) ? 1 : 0) + ((c < gq.y) ? 1 : 0)
                                + ((c < gq.z) ? 1 : 0) + ((c < gq.w) ? 1 : 0);
                    uint4 pb = *(const uint4*)(tSP + (n1 * 8 + j) * 128);
                    Mw[el][0] |= pb.x; Mw[el][1] |= pb.y;
                    Mw[el][2] |= pb.z; Mw[el][3] |= pb.w;
                }
            }
        }

        // ---- Layers 2 + 3, both elements interleaved for ILP ----
        ull m2p[2][4];
#pragma unroll
        for (int k = 0; k < 4; k++) { m2p[0][k] = 0ULL; m2p[1][k] = 0ULL; }
        float mo[2] = {0.f, 0.f}, cnt[2] = {0.f, 0.f};

#pragma unroll
        for (int t = 0; t < 16; t++) {
#pragma unroll
            for (int el = 0; el < 2; el++) {
                unsigned mk = __byte_perm(Mw[el][t >> 2], 0u, 0x4440 | (t & 3));
                float4 A  = *(const float4*)(tA + mk * 128);
                float4 Bv = *(const float4*)(tB + mk * 128);
                ull tp[4] = {pk(A.x, A.y), pk(A.z, A.w), pk(Bv.x, Bv.y), pk(Bv.z, Bv.w)};

                float acc = 0.f;
#pragma unroll
                for (int k = 0; k < 4; k++) {
                    ull v2 = fma2(L2, m2p[el][k], tp[k]);   // per-lane fmaf(0.8, m2, tt)
                    float vl, vh; upk(vl, vh, v2);
                    bool sl = (vl >= TH);
                    if (sl) acc += who[2 * k];
                    vl = sl ? 0.f : vl;
                    bool sh = (vh >= TH);
                    if (sh) acc += who[2 * k + 1];
                    vh = sh ? 0.f : vh;
                    m2p[el][k] = pk(vl, vh);
                }

                float vo = __fadd_rn(fmaf(0.8f, mo[el], acc), bo);
                bool so = (vo >= TH);
                cnt[el] += so ? 1.f : 0.f;
                mo[el] = so ? 0.f : vo;
            }
        }

        out[g] = make_float2(cnt[0] * 0.0625f, cnt[1] * 0.0625f);
    }
}

// Host-side replica of the device fp32 iteration (volatile blocks FMA contraction).
static float host_sim(float c, int n) {
    volatile float u = 0.f;
    for (int k = 0; k < n; k++) { volatile float t = 0.8f * u; u = t + c; }
    return u;
}

extern "C" void kernel_launch(void* const* d_in, const int* in_sizes, int n_in,
                              void* d_out, int out_size) {
    const float4* x2  = (const float4*)d_in[0];
    const float* W_ih = (const float*)d_in[1];
    const float* b_ih = (const float*)d_in[2];
    const float* W_hh = (const float*)d_in[3];
    const float* b_hh = (const float*)d_in[4];
    const float* W_ho = (const float*)d_in[5];
    const float* b_ho = (const float*)d_in[6];

    int B = in_sizes[0] / 2;
    int NP = B / 2;

    Params P;
    // Exact breakpoints via bitwise bisection (monotone in float bits on [0.05, 4]).
    for (int n = 1; n <= 16; n++) {
        float flo = 0.05f, fhi = 4.0f;
        unsigned lo, hi;
        memcpy(&lo, &flo, 4); memcpy(&hi, &fhi, 4);
        while (hi - lo > 1u) {
            unsigned mid = lo + (hi - lo) / 2;
            float fm; memcpy(&fm, &mid, 4);
            if (host_sim(fm, n) >= TH) hi = mid; else lo = mid;
        }
        memcpy(&P.tt[n - 1], &hi, 4);
    }
    for (int n1 = 0; n1 < 17; n1++) {
        unsigned w[4] = {0u, 0u, 0u, 0u};
        int n = n1 + 1;
        if (n <= 16)
            for (int t = 0; t < 16; t++)
                if ((t + 1) % n == 0) w[t >> 2] |= 1u << (8 * (t & 3));
        P.SPb[n1] = make_uint4(w[0], w[1], w[2], w[3]);
    }

    cudaFuncSetAttribute(snn_kernel,
                         cudaFuncAttributeMaxDynamicSharedMemorySize, SMEM_BYTES);

    snn_kernel<<<296, 256, SMEM_BYTES>>>(x2, W_ih, b_ih, W_hh, b_hh, W_ho, b_ho,
                                         (float2*)d_out, NP, P);
}